// round 2
// baseline (speedup 1.0000x reference)
#include <cuda_runtime.h>
#include <cuda_bf16.h>
#include <math.h>

#define N_NODES 100000
#define N_EDGES 3200000
#define K1 489

// ---------------- scratch (device globals; no allocation allowed) ----------
__device__ __align__(256) float g_h1[N_NODES * 64];
__device__ __align__(256) float g_a1[N_NODES * 64];
__device__ __align__(256) float g_h2[N_NODES * 32];
__device__ __align__(256) float g_a2[N_NODES * 32];
__device__ __align__(256) float g_h3[N_NODES * 2];
__device__ __align__(256) float g_a3[N_NODES * 2];
__device__ float g_dinv[N_NODES];
__device__ int   g_deg[N_NODES];

// ---------------- degree / normalization -----------------------------------
__global__ void k_deg_init() {
    int i = blockIdx.x * blockDim.x + threadIdx.x;
    if (i < N_NODES) g_deg[i] = 1;  // self-loop contributes 1
}

__global__ void k_deg_accum(const int* __restrict__ dst) {
    int e = blockIdx.x * blockDim.x + threadIdx.x;
    if (e < N_EDGES) atomicAdd(&g_deg[dst[e]], 1);
}

__global__ void k_dinv() {
    int i = blockIdx.x * blockDim.x + threadIdx.x;
    if (i < N_NODES) g_dinv[i] = rsqrtf((float)g_deg[i]);
}

// ---------------- GEMM1: h1 = x @ W1  (M=100000, K=489, N=64) --------------
// 64x64 tile per block, 256 threads, each thread 4x4 accumulators, BK=32.
__global__ void k_gemm1(const float* __restrict__ X, const float* __restrict__ W) {
    __shared__ float Xs[32][68];   // [k][m], padded
    __shared__ float Ws[32][64];   // [k][n]
    const int tid = threadIdx.x;
    const int tx = tid & 15;
    const int ty = tid >> 4;
    const int blockM = blockIdx.x * 64;

    float acc[4][4] = {};

    for (int k0 = 0; k0 < K1; k0 += 32) {
#pragma unroll
        for (int i = 0; i < 8; i++) {
            int e  = tid + i * 256;
            int kl = e & 31, rl = e >> 5;
            int r = blockM + rl, k = k0 + kl;
            Xs[kl][rl] = (r < N_NODES && k < K1) ? X[(long long)r * K1 + k] : 0.f;
        }
#pragma unroll
        for (int i = 0; i < 8; i++) {
            int e  = tid + i * 256;
            int kl = e >> 6, c = e & 63;
            int k = k0 + kl;
            Ws[kl][c] = (k < K1) ? W[k * 64 + c] : 0.f;
        }
        __syncthreads();
#pragma unroll
        for (int kk = 0; kk < 32; kk++) {
            float xv[4], wv[4];
#pragma unroll
            for (int i = 0; i < 4; i++) xv[i] = Xs[kk][ty * 4 + i];
#pragma unroll
            for (int j = 0; j < 4; j++) wv[j] = Ws[kk][tx * 4 + j];
#pragma unroll
            for (int i = 0; i < 4; i++)
#pragma unroll
                for (int j = 0; j < 4; j++)
                    acc[i][j] = fmaf(xv[i], wv[j], acc[i][j]);
        }
        __syncthreads();
    }
#pragma unroll
    for (int i = 0; i < 4; i++) {
        int r = blockM + ty * 4 + i;
        if (r < N_NODES) {
            float4 v = make_float4(acc[i][0], acc[i][1], acc[i][2], acc[i][3]);
            *(float4*)&g_h1[(long long)r * 64 + tx * 4] = v;
        }
    }
}

// ---------------- self-loop init: a = h * dinv^2 ----------------------------
__global__ void k_selfinit64() {
    int idx = blockIdx.x * blockDim.x + threadIdx.x;   // over N*16 float4s
    if (idx >= N_NODES * 16) return;
    int i = idx >> 4;
    float d = g_dinv[i];
    float s = d * d;
    float4 v = ((const float4*)g_h1)[idx];
    v.x *= s; v.y *= s; v.z *= s; v.w *= s;
    ((float4*)g_a1)[idx] = v;
}

__global__ void k_selfinit32() {
    int idx = blockIdx.x * blockDim.x + threadIdx.x;   // over N*8 float4s
    if (idx >= N_NODES * 8) return;
    int i = idx >> 3;
    float d = g_dinv[i];
    float s = d * d;
    float4 v = ((const float4*)g_h2)[idx];
    v.x *= s; v.y *= s; v.z *= s; v.w *= s;
    ((float4*)g_a2)[idx] = v;
}

__global__ void k_selfinit2() {
    int i = blockIdx.x * blockDim.x + threadIdx.x;
    if (i >= N_NODES) return;
    float d = g_dinv[i];
    float s = d * d;
    float2 v = ((const float2*)g_h3)[i];
    v.x *= s; v.y *= s;
    ((float2*)g_a3)[i] = v;
}

// ---------------- edge scatter: a[dst] += norm * h[src] --------------------
__device__ __forceinline__ void red_v4(float* p, float4 v) {
    asm volatile("red.global.add.v4.f32 [%0], {%1, %2, %3, %4};"
                 :: "l"(p), "f"(v.x), "f"(v.y), "f"(v.z), "f"(v.w) : "memory");
}
__device__ __forceinline__ void red_v2(float* p, float2 v) {
    asm volatile("red.global.add.v2.f32 [%0], {%1, %2};"
                 :: "l"(p), "f"(v.x), "f"(v.y) : "memory");
}

__global__ void k_scatter64(const int* __restrict__ src,
                            const int* __restrict__ dst) {
    long long t = (long long)blockIdx.x * blockDim.x + threadIdx.x;
    int lane = (int)(t & 15);
    long long e = t >> 4;
    if (e >= N_EDGES) return;
    int s = src[e], d = dst[e];
    float nm = g_dinv[s] * g_dinv[d];
    float4 v = ((const float4*)(g_h1 + (long long)s * 64))[lane];
    v.x *= nm; v.y *= nm; v.z *= nm; v.w *= nm;
    red_v4(g_a1 + (long long)d * 64 + lane * 4, v);
}

__global__ void k_scatter32(const int* __restrict__ src,
                            const int* __restrict__ dst) {
    long long t = (long long)blockIdx.x * blockDim.x + threadIdx.x;
    int lane = (int)(t & 7);
    long long e = t >> 3;
    if (e >= N_EDGES) return;
    int s = src[e], d = dst[e];
    float nm = g_dinv[s] * g_dinv[d];
    float4 v = ((const float4*)(g_h2 + (long long)s * 32))[lane];
    v.x *= nm; v.y *= nm; v.z *= nm; v.w *= nm;
    red_v4(g_a2 + (long long)d * 32 + lane * 4, v);
}

__global__ void k_scatter2(const int* __restrict__ src,
                           const int* __restrict__ dst) {
    int e = blockIdx.x * blockDim.x + threadIdx.x;
    if (e >= N_EDGES) return;
    int s = src[e], d = dst[e];
    float nm = g_dinv[s] * g_dinv[d];
    float2 v = ((const float2*)g_h3)[s];
    v.x *= nm; v.y *= nm;
    red_v2(g_a3 + (long long)d * 2, v);
}

// ---------------- GEMM2: h2 = relu(a1 + b1) @ W2  (64 -> 32) ---------------
__global__ void k_gemm2(const float* __restrict__ W2, const float* __restrict__ b1) {
    __shared__ float Ws[64 * 32];
    int tid = threadIdx.x;
    for (int i = tid; i < 64 * 32; i += 256) Ws[i] = W2[i];
    __syncthreads();
    int warp = tid >> 5, lane = tid & 31;
    int row = blockIdx.x * 8 + warp;
    if (row >= N_NODES) return;
    const float* a = g_a1 + (long long)row * 64;
    float r0 = fmaxf(a[lane]      + __ldg(&b1[lane]),      0.f);
    float r1 = fmaxf(a[lane + 32] + __ldg(&b1[lane + 32]), 0.f);
    float acc = 0.f;
#pragma unroll
    for (int k = 0; k < 32; k++) {
        float xv = __shfl_sync(0xffffffffu, r0, k);
        acc = fmaf(xv, Ws[k * 32 + lane], acc);
    }
#pragma unroll
    for (int k = 0; k < 32; k++) {
        float xv = __shfl_sync(0xffffffffu, r1, k);
        acc = fmaf(xv, Ws[(k + 32) * 32 + lane], acc);
    }
    g_h2[(long long)row * 32 + lane] = acc;
}

// ---------------- GEMM3: h3 = relu(a2 + b2) @ W3  (32 -> 2) ----------------
__global__ void k_gemm3(const float* __restrict__ W3, const float* __restrict__ b2) {
    __shared__ float w3[64];
    __shared__ float bb[32];
    if (threadIdx.x < 64) w3[threadIdx.x] = W3[threadIdx.x];
    if (threadIdx.x < 32) bb[threadIdx.x] = b2[threadIdx.x];
    __syncthreads();
    int row = blockIdx.x * blockDim.x + threadIdx.x;
    if (row >= N_NODES) return;
    const float* a = g_a2 + (long long)row * 32;
    float acc0 = 0.f, acc1 = 0.f;
#pragma unroll
    for (int k = 0; k < 32; k++) {
        float h = fmaxf(a[k] + bb[k], 0.f);
        acc0 = fmaf(h, w3[k * 2],     acc0);
        acc1 = fmaf(h, w3[k * 2 + 1], acc1);
    }
    g_h3[(long long)row * 2]     = acc0;
    g_h3[(long long)row * 2 + 1] = acc1;
}

// ---------------- final: out = log_softmax(a3 + b3) ------------------------
__global__ void k_out(const float* __restrict__ b3, float* __restrict__ out) {
    int i = blockIdx.x * blockDim.x + threadIdx.x;
    if (i >= N_NODES) return;
    float z0 = g_a3[2 * i]     + __ldg(&b3[0]);
    float z1 = g_a3[2 * i + 1] + __ldg(&b3[1]);
    float m = fmaxf(z0, z1);
    float lse = m + logf(expf(z0 - m) + expf(z1 - m));
    float2 o = make_float2(z0 - lse, z1 - lse);
    ((float2*)out)[i] = o;
}

// ---------------- launch ----------------------------------------------------
extern "C" void kernel_launch(void* const* d_in, const int* in_sizes, int n_in,
                              void* d_out, int out_size) {
    const float* x  = (const float*)d_in[0];
    const int*   ei = (const int*)d_in[1];     // int32 (JAX x32 default)
    const float* W1 = (const float*)d_in[2];
    const float* b1 = (const float*)d_in[3];
    const float* W2 = (const float*)d_in[4];
    const float* b2 = (const float*)d_in[5];
    const float* W3 = (const float*)d_in[6];
    const float* b3 = (const float*)d_in[7];
    float* out = (float*)d_out;

    const int* src = ei;             // edge_index[0]
    const int* dst = ei + N_EDGES;   // edge_index[1]

    const int TB = 256;
    const int gN = (N_NODES + TB - 1) / TB;
    const int gE = (N_EDGES + TB - 1) / TB;

    // normalization
    k_deg_init<<<gN, TB>>>();
    k_deg_accum<<<gE, TB>>>(dst);
    k_dinv<<<gN, TB>>>();

    // layer 1
    k_gemm1<<<(N_NODES + 63) / 64, TB>>>(x, W1);
    k_selfinit64<<<(N_NODES * 16 + TB - 1) / TB, TB>>>();
    k_scatter64<<<(int)(((long long)N_EDGES * 16 + TB - 1) / TB), TB>>>(src, dst);

    // layer 2
    k_gemm2<<<(N_NODES + 7) / 8, TB>>>(W2, b1);
    k_selfinit32<<<(N_NODES * 8 + TB - 1) / TB, TB>>>();
    k_scatter32<<<(int)(((long long)N_EDGES * 8 + TB - 1) / TB), TB>>>(src, dst);

    // layer 3
    k_gemm3<<<gN, TB>>>(W3, b2);
    k_selfinit2<<<gN, TB>>>();
    k_scatter2<<<gE, TB>>>(src, dst);

    // output
    k_out<<<gN, TB>>>(b3, out);
}

// round 3
// speedup vs baseline: 1.1560x; 1.1560x over previous
#include <cuda_runtime.h>
#include <cuda_bf16.h>
#include <math.h>

#define N_NODES 100000
#define N_EDGES 3200000
#define K1 489

// ---------------- scratch (device globals; no allocation allowed) ----------
// p* = dinv-prescaled messages; a* = aggregation accumulators (init = self loop)
__device__ __align__(256) float g_p1[N_NODES * 64];
__device__ __align__(256) float g_a1[N_NODES * 64];
__device__ __align__(256) float g_p2[N_NODES * 32];
__device__ __align__(256) float g_a2[N_NODES * 32];
__device__ __align__(256) float g_p3[N_NODES * 2];
__device__ __align__(256) float g_a3[N_NODES * 2];
__device__ float g_dinv[N_NODES];
__device__ int   g_deg[N_NODES];

// ---------------- degree / normalization -----------------------------------
__global__ void k_deg_init() {
    int i = blockIdx.x * blockDim.x + threadIdx.x;
    if (i < N_NODES) g_deg[i] = 1;  // self-loop contributes 1
}

__global__ void k_deg_accum(const int* __restrict__ dst) {
    int e = blockIdx.x * blockDim.x + threadIdx.x;
    if (e < N_EDGES) atomicAdd(&g_deg[dst[e]], 1);
}

__global__ void k_dinv() {
    int i = blockIdx.x * blockDim.x + threadIdx.x;
    if (i < N_NODES) g_dinv[i] = rsqrtf((float)g_deg[i]);
}

// ---------------- GEMM1: p1 = dinv .* (x @ W1); a1 = p1 --------------------
// 128x64 tile per block, 256 threads, 8x4 per-thread microtile, BK=16.
__global__ __launch_bounds__(256) void k_gemm1(const float* __restrict__ X,
                                               const float* __restrict__ W) {
    __shared__ float Xs[16][132];   // [k][m] padded
    __shared__ float Ws[16][64];    // [k][n]
    const int tid = threadIdx.x;
    const int tx = tid & 15;        // n group (4 cols)
    const int ty = tid >> 4;        // m group (8 rows)
    const int blockM = blockIdx.x * 128;

    float acc[8][4] = {};

    for (int k0 = 0; k0 < K1; k0 += 16) {
        // X tile: 128 m x 16 k, coalesced along k
#pragma unroll
        for (int i = 0; i < 8; i++) {
            int e  = tid + i * 256;        // 0..2047
            int kl = e & 15, ml = e >> 4;
            int r = blockM + ml, k = k0 + kl;
            Xs[kl][ml] = (r < N_NODES && k < K1) ? X[(long long)r * K1 + k] : 0.f;
        }
        // W tile: 16 k x 64 n, float4 along n
        {
            int kl = tid >> 4, nl = (tid & 15) * 4;
            int k = k0 + kl;
            float4 w = (k < K1) ? *(const float4*)&W[k * 64 + nl]
                                : make_float4(0.f, 0.f, 0.f, 0.f);
            *(float4*)&Ws[kl][nl] = w;
        }
        __syncthreads();
#pragma unroll
        for (int kk = 0; kk < 16; kk++) {
            float xv[8], wv[4];
            *(float4*)&xv[0] = *(const float4*)&Xs[kk][ty * 8];
            *(float4*)&xv[4] = *(const float4*)&Xs[kk][ty * 8 + 4];
            *(float4*)&wv[0] = *(const float4*)&Ws[kk][tx * 4];
#pragma unroll
            for (int i = 0; i < 8; i++)
#pragma unroll
                for (int j = 0; j < 4; j++)
                    acc[i][j] = fmaf(xv[i], wv[j], acc[i][j]);
        }
        __syncthreads();
    }
#pragma unroll
    for (int i = 0; i < 8; i++) {
        int r = blockM + ty * 8 + i;
        if (r < N_NODES) {
            float s = g_dinv[r];
            float4 v = make_float4(acc[i][0] * s, acc[i][1] * s,
                                   acc[i][2] * s, acc[i][3] * s);
            long long off = (long long)r * 64 + tx * 4;
            *(float4*)&g_p1[off] = v;   // message
            *(float4*)&g_a1[off] = v;   // accumulator init (self loop)
        }
    }
}

// ---------------- edge scatter: a[dst] += p[src] (pure) ---------------------
__device__ __forceinline__ void red_v4(float* p, float4 v) {
    asm volatile("red.global.add.v4.f32 [%0], {%1, %2, %3, %4};"
                 :: "l"(p), "f"(v.x), "f"(v.y), "f"(v.z), "f"(v.w) : "memory");
}
__device__ __forceinline__ void red_v2(float* p, float2 v) {
    asm volatile("red.global.add.v2.f32 [%0], {%1, %2};"
                 :: "l"(p), "f"(v.x), "f"(v.y) : "memory");
}

__global__ void k_scatter64(const int* __restrict__ src,
                            const int* __restrict__ dst) {
    long long t = (long long)blockIdx.x * blockDim.x + threadIdx.x;
    int lane = (int)(t & 15);
    long long e = t >> 4;
    if (e >= N_EDGES) return;
    int s = src[e], d = dst[e];
    float4 v = ((const float4*)(g_p1 + (long long)s * 64))[lane];
    red_v4(g_a1 + (long long)d * 64 + lane * 4, v);
}

__global__ void k_scatter32(const int* __restrict__ src,
                            const int* __restrict__ dst) {
    long long t = (long long)blockIdx.x * blockDim.x + threadIdx.x;
    int lane = (int)(t & 7);
    long long e = t >> 3;
    if (e >= N_EDGES) return;
    int s = src[e], d = dst[e];
    float4 v = ((const float4*)(g_p2 + (long long)s * 32))[lane];
    red_v4(g_a2 + (long long)d * 32 + lane * 4, v);
}

__global__ void k_scatter2(const int* __restrict__ src,
                           const int* __restrict__ dst) {
    int e = blockIdx.x * blockDim.x + threadIdx.x;
    if (e >= N_EDGES) return;
    int s = src[e], d = dst[e];
    float2 v = ((const float2*)g_p3)[s];
    red_v2(g_a3 + (long long)d * 2, v);
}

// ---------------- GEMM2: p2 = dinv .* (relu(dinv.*a1 + b1) @ W2); a2 = p2 --
__global__ void k_gemm2(const float* __restrict__ W2, const float* __restrict__ b1) {
    __shared__ float Ws[64 * 32];
    __shared__ float bs[64];
    int tid = threadIdx.x;
    for (int i = tid; i < 64 * 32; i += 256) Ws[i] = W2[i];
    if (tid < 64) bs[tid] = b1[tid];
    __syncthreads();
    int warp = tid >> 5, lane = tid & 31;
    int row = blockIdx.x * 8 + warp;
    if (row >= N_NODES) return;
    float dv = g_dinv[row];
    const float* a = g_a1 + (long long)row * 64;
    float r0 = fmaxf(fmaf(dv, a[lane],      bs[lane]),      0.f);
    float r1 = fmaxf(fmaf(dv, a[lane + 32], bs[lane + 32]), 0.f);
    float acc = 0.f;
#pragma unroll
    for (int k = 0; k < 32; k++) {
        float xv = __shfl_sync(0xffffffffu, r0, k);
        acc = fmaf(xv, Ws[k * 32 + lane], acc);
    }
#pragma unroll
    for (int k = 0; k < 32; k++) {
        float xv = __shfl_sync(0xffffffffu, r1, k);
        acc = fmaf(xv, Ws[(k + 32) * 32 + lane], acc);
    }
    float p = acc * dv;
    long long off = (long long)row * 32 + lane;
    g_p2[off] = p;
    g_a2[off] = p;   // self-loop init
}

// ---------------- GEMM3: p3 = dinv .* (relu(dinv.*a2 + b2) @ W3); a3 = p3 --
__global__ void k_gemm3(const float* __restrict__ W3, const float* __restrict__ b2) {
    __shared__ float w3[64];
    __shared__ float bb[32];
    if (threadIdx.x < 64) w3[threadIdx.x] = W3[threadIdx.x];
    if (threadIdx.x < 32) bb[threadIdx.x] = b2[threadIdx.x];
    __syncthreads();
    int row = blockIdx.x * blockDim.x + threadIdx.x;
    if (row >= N_NODES) return;
    float dv = g_dinv[row];
    const float* a = g_a2 + (long long)row * 32;
    float acc0 = 0.f, acc1 = 0.f;
#pragma unroll
    for (int k = 0; k < 32; k++) {
        float h = fmaxf(fmaf(dv, a[k], bb[k]), 0.f);
        acc0 = fmaf(h, w3[k * 2],     acc0);
        acc1 = fmaf(h, w3[k * 2 + 1], acc1);
    }
    float2 p = make_float2(acc0 * dv, acc1 * dv);
    ((float2*)g_p3)[row] = p;
    ((float2*)g_a3)[row] = p;   // self-loop init
}

// ---------------- final: out = log_softmax(dinv.*a3 + b3) ------------------
__global__ void k_out(const float* __restrict__ b3, float* __restrict__ out) {
    int i = blockIdx.x * blockDim.x + threadIdx.x;
    if (i >= N_NODES) return;
    float dv = g_dinv[i];
    float z0 = fmaf(dv, g_a3[2 * i],     __ldg(&b3[0]));
    float z1 = fmaf(dv, g_a3[2 * i + 1], __ldg(&b3[1]));
    float m = fmaxf(z0, z1);
    float lse = m + logf(expf(z0 - m) + expf(z1 - m));
    ((float2*)out)[i] = make_float2(z0 - lse, z1 - lse);
}

// ---------------- launch ----------------------------------------------------
extern "C" void kernel_launch(void* const* d_in, const int* in_sizes, int n_in,
                              void* d_out, int out_size) {
    const float* x  = (const float*)d_in[0];
    const int*   ei = (const int*)d_in[1];     // int32 (JAX x32 default)
    const float* W1 = (const float*)d_in[2];
    const float* b1 = (const float*)d_in[3];
    const float* W2 = (const float*)d_in[4];
    const float* b2 = (const float*)d_in[5];
    const float* W3 = (const float*)d_in[6];
    const float* b3 = (const float*)d_in[7];
    float* out = (float*)d_out;

    const int* src = ei;             // edge_index[0]
    const int* dst = ei + N_EDGES;   // edge_index[1]

    const int TB = 256;
    const int gN = (N_NODES + TB - 1) / TB;
    const int gE = (N_EDGES + TB - 1) / TB;

    // normalization
    k_deg_init<<<gN, TB>>>();
    k_deg_accum<<<gE, TB>>>(dst);
    k_dinv<<<gN, TB>>>();

    // layer 1
    k_gemm1<<<(N_NODES + 127) / 128, TB>>>(x, W1);
    k_scatter64<<<(int)(((long long)N_EDGES * 16 + TB - 1) / TB), TB>>>(src, dst);

    // layer 2
    k_gemm2<<<(N_NODES + 7) / 8, TB>>>(W2, b1);
    k_scatter32<<<(int)(((long long)N_EDGES * 8 + TB - 1) / TB), TB>>>(src, dst);

    // layer 3
    k_gemm3<<<gN, TB>>>(W3, b2);
    k_scatter2<<<gE, TB>>>(src, dst);

    // output
    k_out<<<gN, TB>>>(b3, out);
}

// round 4
// speedup vs baseline: 1.5525x; 1.3429x over previous
#include <cuda_runtime.h>
#include <cuda_bf16.h>
#include <math.h>

#define N_NODES 100000
#define N_EDGES 3200000
#define K1 489

// ---------------- scratch (device globals; no allocation allowed) ----------
// p* = dinv-prescaled messages; a* = aggregated (self loop + neighbors)
__device__ __align__(256) float g_p1[N_NODES * 64];
__device__ __align__(256) float g_a1[N_NODES * 64];
__device__ __align__(256) float g_p2[N_NODES * 32];
__device__ __align__(256) float g_a2[N_NODES * 32];
__device__ __align__(256) float g_p3[N_NODES * 2];
__device__ __align__(256) float g_a3[N_NODES * 2];
__device__ float g_dinv[N_NODES];

// CSR (incoming edges, unordered row placement)
__device__ int g_cnt[N_NODES];     // in-degree (edges only)
__device__ int g_start[N_NODES];   // row start in g_csr
__device__ int g_cursor[N_NODES];  // fill cursor
__device__ int g_head;             // global allocation head
__device__ int g_csr[N_EDGES];     // src ids grouped by dst

// ---------------- CSR build -------------------------------------------------
__global__ void k_init() {
    int i = blockIdx.x * blockDim.x + threadIdx.x;
    if (i < N_NODES) g_cnt[i] = 0;
    if (i == 0) g_head = 0;
}

__global__ void k_cnt(const int* __restrict__ dst) {
    int e = blockIdx.x * blockDim.x + threadIdx.x;
    if (e < N_EDGES) atomicAdd(&g_cnt[dst[e]], 1);
}

__global__ void k_alloc() {
    int i = blockIdx.x * blockDim.x + threadIdx.x;
    if (i >= N_NODES) return;
    int c = g_cnt[i];
    int s = atomicAdd(&g_head, c);
    g_start[i]  = s;
    g_cursor[i] = s;
    g_dinv[i]   = rsqrtf((float)(c + 1));   // +1 self loop
}

__global__ void k_fill(const int* __restrict__ src, const int* __restrict__ dst) {
    int e = blockIdx.x * blockDim.x + threadIdx.x;
    if (e >= N_EDGES) return;
    int d = dst[e];
    int pos = atomicAdd(&g_cursor[d], 1);
    g_csr[pos] = src[e];
}

// ---------------- GEMM1: p1 = dinv .* (x @ W1) ------------------------------
// 128x64 tile per block, 256 threads, 8x4 per-thread microtile, BK=16.
__global__ __launch_bounds__(256) void k_gemm1(const float* __restrict__ X,
                                               const float* __restrict__ W) {
    __shared__ float Xs[16][132];   // [k][m] padded
    __shared__ float Ws[16][64];    // [k][n]
    const int tid = threadIdx.x;
    const int tx = tid & 15;
    const int ty = tid >> 4;
    const int blockM = blockIdx.x * 128;

    float acc[8][4] = {};

    for (int k0 = 0; k0 < K1; k0 += 16) {
#pragma unroll
        for (int i = 0; i < 8; i++) {
            int e  = tid + i * 256;
            int kl = e & 15, ml = e >> 4;
            int r = blockM + ml, k = k0 + kl;
            Xs[kl][ml] = (r < N_NODES && k < K1) ? X[(long long)r * K1 + k] : 0.f;
        }
        {
            int kl = tid >> 4, nl = (tid & 15) * 4;
            int k = k0 + kl;
            float4 w = (k < K1) ? *(const float4*)&W[k * 64 + nl]
                                : make_float4(0.f, 0.f, 0.f, 0.f);
            *(float4*)&Ws[kl][nl] = w;
        }
        __syncthreads();
#pragma unroll
        for (int kk = 0; kk < 16; kk++) {
            float xv[8], wv[4];
            *(float4*)&xv[0] = *(const float4*)&Xs[kk][ty * 8];
            *(float4*)&xv[4] = *(const float4*)&Xs[kk][ty * 8 + 4];
            *(float4*)&wv[0] = *(const float4*)&Ws[kk][tx * 4];
#pragma unroll
            for (int i = 0; i < 8; i++)
#pragma unroll
                for (int j = 0; j < 4; j++)
                    acc[i][j] = fmaf(xv[i], wv[j], acc[i][j]);
        }
        __syncthreads();
    }
#pragma unroll
    for (int i = 0; i < 8; i++) {
        int r = blockM + ty * 8 + i;
        if (r < N_NODES) {
            float s = g_dinv[r];
            float4 v = make_float4(acc[i][0] * s, acc[i][1] * s,
                                   acc[i][2] * s, acc[i][3] * s);
            *(float4*)&g_p1[(long long)r * 64 + tx * 4] = v;
        }
    }
}

// ---------------- gather: a[d] = p[d] + sum_{s in N(d)} p[s] ----------------
__global__ __launch_bounds__(256) void k_gather64() {
    int t = blockIdx.x * blockDim.x + threadIdx.x;
    int node = t >> 4, lane = t & 15;
    if (node >= N_NODES) return;
    const float4* P = (const float4*)g_p1;
    float4 v = P[node * 16 + lane];   // self loop
    int beg = g_start[node], n = g_cnt[node];
    int j = 0;
    for (; j + 4 <= n; j += 4) {
        int s0 = g_csr[beg + j],     s1 = g_csr[beg + j + 1];
        int s2 = g_csr[beg + j + 2], s3 = g_csr[beg + j + 3];
        float4 u0 = __ldg(P + s0 * 16 + lane);
        float4 u1 = __ldg(P + s1 * 16 + lane);
        float4 u2 = __ldg(P + s2 * 16 + lane);
        float4 u3 = __ldg(P + s3 * 16 + lane);
        v.x += (u0.x + u1.x) + (u2.x + u3.x);
        v.y += (u0.y + u1.y) + (u2.y + u3.y);
        v.z += (u0.z + u1.z) + (u2.z + u3.z);
        v.w += (u0.w + u1.w) + (u2.w + u3.w);
    }
    for (; j < n; j++) {
        int s = g_csr[beg + j];
        float4 u = __ldg(P + s * 16 + lane);
        v.x += u.x; v.y += u.y; v.z += u.z; v.w += u.w;
    }
    ((float4*)g_a1)[node * 16 + lane] = v;
}

__global__ __launch_bounds__(256) void k_gather32() {
    int t = blockIdx.x * blockDim.x + threadIdx.x;
    int node = t >> 3, lane = t & 7;
    if (node >= N_NODES) return;
    const float4* P = (const float4*)g_p2;
    float4 v = P[node * 8 + lane];
    int beg = g_start[node], n = g_cnt[node];
    int j = 0;
    for (; j + 4 <= n; j += 4) {
        int s0 = g_csr[beg + j],     s1 = g_csr[beg + j + 1];
        int s2 = g_csr[beg + j + 2], s3 = g_csr[beg + j + 3];
        float4 u0 = __ldg(P + s0 * 8 + lane);
        float4 u1 = __ldg(P + s1 * 8 + lane);
        float4 u2 = __ldg(P + s2 * 8 + lane);
        float4 u3 = __ldg(P + s3 * 8 + lane);
        v.x += (u0.x + u1.x) + (u2.x + u3.x);
        v.y += (u0.y + u1.y) + (u2.y + u3.y);
        v.z += (u0.z + u1.z) + (u2.z + u3.z);
        v.w += (u0.w + u1.w) + (u2.w + u3.w);
    }
    for (; j < n; j++) {
        int s = g_csr[beg + j];
        float4 u = __ldg(P + s * 8 + lane);
        v.x += u.x; v.y += u.y; v.z += u.z; v.w += u.w;
    }
    ((float4*)g_a2)[node * 8 + lane] = v;
}

__global__ __launch_bounds__(256) void k_gather2() {
    int node = blockIdx.x * blockDim.x + threadIdx.x;
    if (node >= N_NODES) return;
    const float2* P = (const float2*)g_p3;
    float2 v = P[node];
    int beg = g_start[node], n = g_cnt[node];
    int j = 0;
    for (; j + 4 <= n; j += 4) {
        int s0 = g_csr[beg + j],     s1 = g_csr[beg + j + 1];
        int s2 = g_csr[beg + j + 2], s3 = g_csr[beg + j + 3];
        float2 u0 = __ldg(P + s0), u1 = __ldg(P + s1);
        float2 u2 = __ldg(P + s2), u3 = __ldg(P + s3);
        v.x += (u0.x + u1.x) + (u2.x + u3.x);
        v.y += (u0.y + u1.y) + (u2.y + u3.y);
    }
    for (; j < n; j++) {
        float2 u = __ldg(P + g_csr[beg + j]);
        v.x += u.x; v.y += u.y;
    }
    ((float2*)g_a3)[node] = v;
}

// ---------------- GEMM2: p2 = dinv .* (relu(dinv.*a1 + b1) @ W2) -----------
__global__ void k_gemm2(const float* __restrict__ W2, const float* __restrict__ b1) {
    __shared__ float Ws[64 * 32];
    __shared__ float bs[64];
    int tid = threadIdx.x;
    for (int i = tid; i < 64 * 32; i += 256) Ws[i] = W2[i];
    if (tid < 64) bs[tid] = b1[tid];
    __syncthreads();
    int warp = tid >> 5, lane = tid & 31;
    int row = blockIdx.x * 8 + warp;
    if (row >= N_NODES) return;
    float dv = g_dinv[row];
    const float* a = g_a1 + (long long)row * 64;
    float r0 = fmaxf(fmaf(dv, a[lane],      bs[lane]),      0.f);
    float r1 = fmaxf(fmaf(dv, a[lane + 32], bs[lane + 32]), 0.f);
    float acc = 0.f;
#pragma unroll
    for (int k = 0; k < 32; k++) {
        float xv = __shfl_sync(0xffffffffu, r0, k);
        acc = fmaf(xv, Ws[k * 32 + lane], acc);
    }
#pragma unroll
    for (int k = 0; k < 32; k++) {
        float xv = __shfl_sync(0xffffffffu, r1, k);
        acc = fmaf(xv, Ws[(k + 32) * 32 + lane], acc);
    }
    g_p2[(long long)row * 32 + lane] = acc * dv;
}

// ---------------- GEMM3: p3 = dinv .* (relu(dinv.*a2 + b2) @ W3) -----------
__global__ void k_gemm3(const float* __restrict__ W3, const float* __restrict__ b2) {
    __shared__ float w3[64];
    __shared__ float bb[32];
    if (threadIdx.x < 64) w3[threadIdx.x] = W3[threadIdx.x];
    if (threadIdx.x < 32) bb[threadIdx.x] = b2[threadIdx.x];
    __syncthreads();
    int row = blockIdx.x * blockDim.x + threadIdx.x;
    if (row >= N_NODES) return;
    float dv = g_dinv[row];
    const float* a = g_a2 + (long long)row * 32;
    float acc0 = 0.f, acc1 = 0.f;
#pragma unroll
    for (int k = 0; k < 32; k++) {
        float h = fmaxf(fmaf(dv, a[k], bb[k]), 0.f);
        acc0 = fmaf(h, w3[k * 2],     acc0);
        acc1 = fmaf(h, w3[k * 2 + 1], acc1);
    }
    ((float2*)g_p3)[row] = make_float2(acc0 * dv, acc1 * dv);
}

// ---------------- final: out = log_softmax(dinv.*a3 + b3) ------------------
__global__ void k_out(const float* __restrict__ b3, float* __restrict__ out) {
    int i = blockIdx.x * blockDim.x + threadIdx.x;
    if (i >= N_NODES) return;
    float dv = g_dinv[i];
    float z0 = fmaf(dv, g_a3[2 * i],     __ldg(&b3[0]));
    float z1 = fmaf(dv, g_a3[2 * i + 1], __ldg(&b3[1]));
    float m = fmaxf(z0, z1);
    float lse = m + logf(expf(z0 - m) + expf(z1 - m));
    ((float2*)out)[i] = make_float2(z0 - lse, z1 - lse);
}

// ---------------- launch ----------------------------------------------------
extern "C" void kernel_launch(void* const* d_in, const int* in_sizes, int n_in,
                              void* d_out, int out_size) {
    const float* x  = (const float*)d_in[0];
    const int*   ei = (const int*)d_in[1];
    const float* W1 = (const float*)d_in[2];
    const float* b1 = (const float*)d_in[3];
    const float* W2 = (const float*)d_in[4];
    const float* b2 = (const float*)d_in[5];
    const float* W3 = (const float*)d_in[6];
    const float* b3 = (const float*)d_in[7];
    float* out = (float*)d_out;

    const int* src = ei;             // edge_index[0]
    const int* dst = ei + N_EDGES;   // edge_index[1]

    const int TB = 256;
    const int gN = (N_NODES + TB - 1) / TB;
    const int gE = (N_EDGES + TB - 1) / TB;

    // CSR build (also produces dinv); overlaps nothing, reused by all layers
    k_init<<<gN, TB>>>();
    k_cnt<<<gE, TB>>>(dst);
    k_alloc<<<gN, TB>>>();
    k_fill<<<gE, TB>>>(src, dst);

    // layer 1
    k_gemm1<<<(N_NODES + 127) / 128, TB>>>(x, W1);
    k_gather64<<<(N_NODES * 16 + TB - 1) / TB, TB>>>();

    // layer 2
    k_gemm2<<<(N_NODES + 7) / 8, TB>>>(W2, b1);
    k_gather32<<<(N_NODES * 8 + TB - 1) / TB, TB>>>();

    // layer 3
    k_gemm3<<<gN, TB>>>(W3, b2);
    k_gather2<<<gN, TB>>>();

    // output
    k_out<<<gN, TB>>>(b3, out);
}